// round 4
// baseline (speedup 1.0000x reference)
#include <cuda_runtime.h>

#define BSZ 4
#define SEQ 256
#define DIM 128
#define HID 128
#define DFF 512
#define MROWS (BSZ*SEQ)   // 1024
#define LGSZ (BSZ*SEQ*SEQ)

// ---------------- scratch (device globals; no allocations) ----------------
__device__ float g_Wbig1[DIM*384];
__device__ float g_Wbig2[DIM*384];
__device__ float g_bbig1[384];
__device__ float g_bbig2[384];
__device__ float g_buf1[MROWS*384];   // [v1 | T1A | T1B]
__device__ float g_buf2[MROWS*384];   // [pk | TkA | TkB]
__device__ float g_Tq  [MROWS*256];   // [TqA | TqB]
__device__ float g_lg  [8*LGSZ];      // sim partials
__device__ float g_probs[LGSZ];
__device__ float g_ctx[MROWS*DIM];
__device__ float g_o1 [MROWS*DIM];
__device__ float g_o2 [MROWS*DIM];
__device__ float g_fh [MROWS*DFF];

// ---------------- prep: biases  bbig = [bw | bw@Wcat + [b1|0]] -------------
__global__ void prep_bias_kernel(const float* __restrict__ bw1, const float* __restrict__ bw2,
                                 const float* __restrict__ W1q, const float* __restrict__ W1k,
                                 const float* __restrict__ b1,
                                 float* __restrict__ bbig1, float* __restrict__ bbig2)
{
    const float* bw = blockIdx.x ? bw2 : bw1;
    float* outp = blockIdx.x ? bbig2 : bbig1;
    int n = threadIdx.x;                 // 0..383
    if (n < 128) { outp[n] = bw[n]; return; }
    int np = n - 128;
    const float* Wsrc = (np < 128) ? W1q : W1k;
    int col = np & 127;
    float s = (np < 128) ? b1[col] : 0.f;
    for (int k = 0; k < 128; k++) s += bw[k] * Wsrc[k * 128 + col];
    outp[n] = s;
}

// ---------------- prep: Wbig = [Ww | Ww@W1q | Ww@W1k]  (128x384) -----------
__global__ void prep_wbig_kernel(const float* __restrict__ Ww1, const float* __restrict__ Ww2,
                                 const float* __restrict__ W1q, const float* __restrict__ W1k,
                                 float* __restrict__ Wbig1, float* __restrict__ Wbig2)
{
    const float* Ww = blockIdx.z ? Ww2 : Ww1;
    float* Wbig = blockIdx.z ? Wbig2 : Wbig1;
    int bx = blockIdx.x, m0 = blockIdx.y * 32;
    int tid = threadIdx.x;
    if (bx < 4) {                        // copy Ww into cols [0,128)
        int n0 = bx * 32;
        for (int idx = tid; idx < 1024; idx += 256) {
            int mm = idx >> 5, nn = idx & 31;
            Wbig[(m0 + mm) * 384 + n0 + nn] = Ww[(m0 + mm) * 128 + n0 + nn];
        }
        return;
    }
    // GEMM tile: cols [128 + n0p, +32) = Ww @ Wcat[:, n0p:n0p+32]
    int n0p = (bx - 4) * 32;
    const float* Bsrc = (n0p < 128) ? (W1q + n0p) : (W1k + n0p - 128);
    __shared__ float As[32][34], Bs[32][34];
    int tx = tid & 15, ty = tid >> 4;
    float a00 = 0.f, a01 = 0.f, a10 = 0.f, a11 = 0.f;
    for (int k0 = 0; k0 < 128; k0 += 32) {
        #pragma unroll
        for (int i = 0; i < 4; i++) {
            int idx = tid + i * 256;
            int ka = idx & 31, ma = idx >> 5;
            As[ka][ma] = Ww[(m0 + ma) * 128 + k0 + ka];
            int nb = idx & 31, kb = idx >> 5;
            Bs[kb][nb] = Bsrc[(k0 + kb) * 128 + nb];
        }
        __syncthreads();
        #pragma unroll
        for (int kk = 0; kk < 32; kk++) {
            float2 a = *(const float2*)&As[kk][ty * 2];
            float2 b = *(const float2*)&Bs[kk][tx * 2];
            a00 += a.x * b.x; a01 += a.x * b.y;
            a10 += a.y * b.x; a11 += a.y * b.y;
        }
        __syncthreads();
    }
    int m = m0 + ty * 2, n = 128 + n0p + tx * 2;
    Wbig[m * 384 + n]           = a00;
    Wbig[m * 384 + n + 1]       = a01;
    Wbig[(m + 1) * 384 + n]     = a10;
    Wbig[(m + 1) * 384 + n + 1] = a11;
}

// ---------------- generalized SGEMM, 32x32 tile, 256 thr, double-buffered --
// set0 used with z-strides; set1 (if C1) used when blockIdx.z==1.
__global__ void sgemm_kernel(const float* __restrict__ A0, const float* __restrict__ B0,
                             const float* __restrict__ bias0, float* __restrict__ C0,
                             const float* __restrict__ A1, const float* __restrict__ B1,
                             const float* __restrict__ bias1, float* __restrict__ C1,
                             int K, int lda, int ldb, int ldc,
                             long sA, long sB, long sC, int relu)
{
    __shared__ float As[2][32][34];
    __shared__ float Bs[2][32][34];
    int z = blockIdx.z;
    bool use1 = (z == 1) && (C1 != 0);
    const float* A = use1 ? A1 : A0 + (long)z * sA;
    const float* B = use1 ? B1 : B0 + (long)z * sB;
    const float* bias = use1 ? bias1 : bias0;
    float* C = use1 ? C1 : C0 + (long)z * sC;
    int m0 = blockIdx.y * 32, n0 = blockIdx.x * 32;
    int tid = threadIdx.x;
    int tx = tid & 15, ty = tid >> 4;
    int lr = tid >> 5, lc = tid & 31;          // load row/col within tile
    const float* Aptr = A + (long)(m0 + lr) * lda + lc;
    const float* Bptr = B + (long)lr * ldb + n0 + lc;
    float acc00 = 0.f, acc01 = 0.f, acc10 = 0.f, acc11 = 0.f;
    float ra[4], rb[4];

    #pragma unroll
    for (int i = 0; i < 4; i++) {
        ra[i] = Aptr[(long)i * 8 * lda];
        rb[i] = Bptr[(long)i * 8 * ldb];
    }
    #pragma unroll
    for (int i = 0; i < 4; i++) {
        As[0][lc][lr + 8 * i] = ra[i];
        Bs[0][lr + 8 * i][lc] = rb[i];
    }
    __syncthreads();

    int s = 0;
    for (int k0 = 32; ; k0 += 32) {
        bool more = (k0 < K);
        if (more) {
            Aptr += 32;
            Bptr += (long)32 * ldb;
            #pragma unroll
            for (int i = 0; i < 4; i++) {
                ra[i] = Aptr[(long)i * 8 * lda];
                rb[i] = Bptr[(long)i * 8 * ldb];
            }
        }
        #pragma unroll
        for (int kk = 0; kk < 32; kk++) {
            float2 a = *(const float2*)&As[s][kk][ty * 2];
            float2 b = *(const float2*)&Bs[s][kk][tx * 2];
            acc00 += a.x * b.x; acc01 += a.x * b.y;
            acc10 += a.y * b.x; acc11 += a.y * b.y;
        }
        if (!more) break;
        #pragma unroll
        for (int i = 0; i < 4; i++) {
            As[s ^ 1][lc][lr + 8 * i] = ra[i];
            Bs[s ^ 1][lr + 8 * i][lc] = rb[i];
        }
        __syncthreads();
        s ^= 1;
    }

    int m = m0 + ty * 2, n = n0 + tx * 2;
    float bb0 = bias ? bias[n]     : 0.f;
    float bb1 = bias ? bias[n + 1] : 0.f;
    float v00 = acc00 + bb0, v01 = acc01 + bb1;
    float v10 = acc10 + bb0, v11 = acc11 + bb1;
    if (relu) {
        v00 = fmaxf(v00, 0.f); v01 = fmaxf(v01, 0.f);
        v10 = fmaxf(v10, 0.f); v11 = fmaxf(v11, 0.f);
    }
    C[(long)m * ldc + n]           = v00;
    C[(long)m * ldc + n + 1]       = v01;
    C[(long)(m + 1) * ldc + n]     = v10;
    C[(long)(m + 1) * ldc + n + 1] = v11;
}

// ---------------- pairwise similarity: 64x64 tile, 4x4 micro ---------------
// q rows at qbase (stride ldq): A-part at +0, B-part at +128. Same for kbase.
// term1 = relu(Aq + Bk).W2 ; term2 (dual) = relu(Ak + Bq).W2
// z = b*(128/hch) + hq ; partial h-chunk [h0, h0+hch) -> lg + hq*LGSZ.
__global__ void sim_kernel(const float* __restrict__ qbase, int ldq,
                           const float* __restrict__ kbase, int ldk,
                           const float* __restrict__ W2,
                           float* __restrict__ lg, int dual, int hch)
{
    __shared__ float sqa[32][68], sqb[32][68];
    __shared__ float ska[32][68], skb[32][68];
    __shared__ float sw[32];
    int nch = 128 / hch;
    int z = blockIdx.z, b = z / nch, hq = z % nch;
    int h0 = hq * hch;
    int q0 = blockIdx.y * 64, k0 = blockIdx.x * 64;
    const float* qp = qbase + (long)(b * SEQ + q0) * ldq;
    const float* kp = kbase + (long)(b * SEQ + k0) * ldk;
    int tid = threadIdx.x, tx = tid & 15, ty = tid >> 4;
    int sh = (hch == 32) ? 5 : 4, hm = hch - 1;
    float acc[4][4] = {};

    for (int idx = tid; idx < 64 * hch; idx += 256) {
        int h = idx & hm, r = idx >> sh;
        sqa[h][r] = qp[(long)r * ldq + h0 + h];
        skb[h][r] = kp[(long)r * ldk + 128 + h0 + h];
        if (dual) {
            sqb[h][r] = qp[(long)r * ldq + 128 + h0 + h];
            ska[h][r] = kp[(long)r * ldk + h0 + h];
        }
    }
    if (tid < hch) sw[tid] = W2[h0 + tid];
    __syncthreads();

    for (int h = 0; h < hch; h++) {
        float w = sw[h];
        float4 qa = *(const float4*)&sqa[h][ty * 4];
        float4 kb = *(const float4*)&skb[h][tx * 4];
        float qv[4] = {qa.x, qa.y, qa.z, qa.w};
        float kv[4] = {kb.x, kb.y, kb.z, kb.w};
        #pragma unroll
        for (int i = 0; i < 4; i++)
            #pragma unroll
            for (int j = 0; j < 4; j++)
                acc[i][j] += fmaxf(qv[i] + kv[j], 0.f) * w;
        if (dual) {
            float4 qb4 = *(const float4*)&sqb[h][ty * 4];
            float4 ka4 = *(const float4*)&ska[h][tx * 4];
            float qbv[4] = {qb4.x, qb4.y, qb4.z, qb4.w};
            float kav[4] = {ka4.x, ka4.y, ka4.z, ka4.w};
            #pragma unroll
            for (int i = 0; i < 4; i++)
                #pragma unroll
                for (int j = 0; j < 4; j++)
                    acc[i][j] += fmaxf(kav[j] + qbv[i], 0.f) * w;
        }
    }

    float* outp = lg + (long)hq * LGSZ;
    #pragma unroll
    for (int i = 0; i < 4; i++) {
        int q = q0 + ty * 4 + i;
        float4 o4 = {acc[i][0], acc[i][1], acc[i][2], acc[i][3]};
        *(float4*)&outp[((long)b * SEQ + q) * SEQ + k0 + tx * 4] = o4;
    }
}

// ---------------- masked softmax; sums npart partials; sym adds transpose --
__global__ void softmax_kernel(const float* __restrict__ lg,
                               const float* __restrict__ mask, const float* __restrict__ b2p,
                               float* __restrict__ probs, int sym, int npart)
{
    int q = blockIdx.x, b = blockIdx.y;
    long row = ((long)b * SEQ + q) * SEQ;
    int t = threadIdx.x;
    __shared__ float red[8];

    float x = 0.f;
    for (int p = 0; p < npart; p++) x += lg[(long)p * LGSZ + row + t];
    if (sym) {
        long col = ((long)b * SEQ + t) * SEQ + q;
        for (int p = 0; p < npart; p++) x += lg[(long)p * LGSZ + col];
    }
    x += 2.f * b2p[0] + mask[row + t] * (-1e9f);

    float m = x;
    #pragma unroll
    for (int o = 16; o; o >>= 1) m = fmaxf(m, __shfl_xor_sync(0xffffffffu, m, o));
    if ((t & 31) == 0) red[t >> 5] = m;
    __syncthreads();
    m = red[0];
    #pragma unroll
    for (int i = 1; i < 8; i++) m = fmaxf(m, red[i]);

    float e = __expf(x - m);
    float s = e;
    #pragma unroll
    for (int o = 16; o; o >>= 1) s += __shfl_xor_sync(0xffffffffu, s, o);
    __syncthreads();
    if ((t & 31) == 0) red[t >> 5] = s;
    __syncthreads();
    s = red[0] + red[1] + red[2] + red[3] + red[4] + red[5] + red[6] + red[7];
    probs[row + t] = e / s;
}

// ---------------- fused GEMM + bias + residual + LayerNorm -----------------
// out[M,128] = LN(A[M,K]@B[K,128] + bias + res). 8 rows/block, 256 threads.
__global__ void gemm_ln_kernel(const float* __restrict__ A, const float* __restrict__ B,
                               const float* __restrict__ bias, const float* __restrict__ res,
                               const float* __restrict__ g, const float* __restrict__ be,
                               float* __restrict__ out, int K)
{
    __shared__ float As[32][8];      // [k][m]
    __shared__ float Bs[32][132];    // [k][n]
    int m0 = blockIdx.x * 8;
    int tid = threadIdx.x;
    int tr = tid >> 5, tc = tid & 31;    // row tr, cols tc*4..+3
    float acc[4] = {};

    for (int k0 = 0; k0 < K; k0 += 32) {
        {
            int k = tid & 31, mm = tid >> 5;
            As[k][mm] = A[(long)(m0 + mm) * K + k0 + k];
        }
        #pragma unroll
        for (int i = 0; i < 4; i++) {
            int idx = tid + i * 256;         // float4 units 0..1023
            int n4 = idx & 31, kb = idx >> 5;
            *(float4*)&Bs[kb][n4 * 4] = *(const float4*)&B[(long)(k0 + kb) * 128 + n4 * 4];
        }
        __syncthreads();
        #pragma unroll
        for (int kk = 0; kk < 32; kk++) {
            float a = As[kk][tr];
            float4 b = *(const float4*)&Bs[kk][tc * 4];
            acc[0] += a * b.x; acc[1] += a * b.y;
            acc[2] += a * b.z; acc[3] += a * b.w;
        }
        __syncthreads();
    }

    int r = m0 + tr;
    float v[4];
    #pragma unroll
    for (int j = 0; j < 4; j++) {
        int n = tc * 4 + j;
        v[j] = acc[j] + bias[n] + res[(long)r * 128 + n];
    }
    float s = v[0] + v[1] + v[2] + v[3];
    #pragma unroll
    for (int o = 16; o; o >>= 1) s += __shfl_xor_sync(0xffffffffu, s, o);
    float mean = s * (1.f / 128.f);
    float vs = 0.f;
    #pragma unroll
    for (int j = 0; j < 4; j++) { float d = v[j] - mean; vs += d * d; }
    #pragma unroll
    for (int o = 16; o; o >>= 1) vs += __shfl_xor_sync(0xffffffffu, vs, o);
    float inv = rsqrtf(vs * (1.f / 128.f) + 1e-6f);
    #pragma unroll
    for (int j = 0; j < 4; j++) {
        int n = tc * 4 + j;
        out[(long)r * 128 + n] = (v[j] - mean) * inv * g[n] + be[n];
    }
}

// ---------------- host orchestration ----------------
extern "C" void kernel_launch(void* const* d_in, const int* in_sizes, int n_in,
                              void* d_out, int out_size)
{
    (void)in_sizes; (void)n_in; (void)out_size;
    const float* x    = (const float*)d_in[0];
    const float* enc  = (const float*)d_in[1];
    const float* cmsk = (const float*)d_in[2];
    const float* dmsk = (const float*)d_in[3];
    const float* W1q  = (const float*)d_in[4];
    const float* W1k  = (const float*)d_in[5];
    const float* b1   = (const float*)d_in[6];
    const float* W2   = (const float*)d_in[7];
    const float* b2   = (const float*)d_in[8];
    const float* Ww1  = (const float*)d_in[9];
    const float* bw1  = (const float*)d_in[10];
    const float* Wd1  = (const float*)d_in[11];
    const float* bd1  = (const float*)d_in[12];
    const float* Ww2  = (const float*)d_in[13];
    const float* bw2  = (const float*)d_in[14];
    const float* Wd2  = (const float*)d_in[15];
    const float* bd2  = (const float*)d_in[16];
    const float* Wf1  = (const float*)d_in[17];
    const float* bf1  = (const float*)d_in[18];
    const float* Wf2  = (const float*)d_in[19];
    const float* bf2  = (const float*)d_in[20];
    const float* ln1g = (const float*)d_in[21];
    const float* ln1b = (const float*)d_in[22];
    const float* ln2g = (const float*)d_in[23];
    const float* ln2b = (const float*)d_in[24];
    const float* ln3g = (const float*)d_in[25];
    const float* ln3b = (const float*)d_in[26];
    float* out = (float*)d_out;

    float *Wb1, *Wb2, *bb1, *bb2, *buf1, *buf2, *Tq, *lg, *probs, *ctx, *o1, *o2, *fh;
    cudaGetSymbolAddress((void**)&Wb1,   g_Wbig1);
    cudaGetSymbolAddress((void**)&Wb2,   g_Wbig2);
    cudaGetSymbolAddress((void**)&bb1,   g_bbig1);
    cudaGetSymbolAddress((void**)&bb2,   g_bbig2);
    cudaGetSymbolAddress((void**)&buf1,  g_buf1);
    cudaGetSymbolAddress((void**)&buf2,  g_buf2);
    cudaGetSymbolAddress((void**)&Tq,    g_Tq);
    cudaGetSymbolAddress((void**)&lg,    g_lg);
    cudaGetSymbolAddress((void**)&probs, g_probs);
    cudaGetSymbolAddress((void**)&ctx,   g_ctx);
    cudaGetSymbolAddress((void**)&o1,    g_o1);
    cudaGetSymbolAddress((void**)&o2,    g_o2);
    cudaGetSymbolAddress((void**)&fh,    g_fh);

    dim3 smGrid(SEQ, BSZ);

    // ---- prep (weights only) ----
    prep_bias_kernel<<<2, 384>>>(bw1, bw2, W1q, W1k, b1, bb1, bb2);
    prep_wbig_kernel<<<dim3(12, 4, 2), 256>>>(Ww1, Ww2, W1q, W1k, Wb1, Wb2);

    // ---- batched projection: buf1 = x@Wbig1, buf2 = enc@Wbig2 ----
    sgemm_kernel<<<dim3(12, 32, 2), 256>>>(x, Wb1, bb1, buf1,
                                           enc, Wb2, bb2, buf2,
                                           128, 128, 384, 384, 0, 0, 0, 0);

    // ---- self-attention: logits = S + S^T ----
    sim_kernel<<<dim3(4, 4, 16), 256>>>(buf1 + 128, 384, buf1 + 128, 384, W2, lg, 0, 32);
    softmax_kernel<<<smGrid, 256>>>(lg, cmsk, b2, probs, 1, 4);
    sgemm_kernel<<<dim3(4, 8, 4), 256>>>(probs, buf1, 0, ctx, 0, 0, 0, 0,
                                         256, 256, 384, 128,
                                         (long)SEQ * SEQ, (long)SEQ * 384, (long)SEQ * 128, 0);
    gemm_ln_kernel<<<MROWS / 8, 256>>>(ctx, Wd1, bd1, x, ln1g, ln1b, o1, 128);

    // ---- cross-attention ----
    sgemm_kernel<<<dim3(8, 32, 1), 256>>>(o1, Wb2 + 128, bb2 + 128, Tq, 0, 0, 0, 0,
                                          128, 128, 384, 256, 0, 0, 0, 0);
    sim_kernel<<<dim3(4, 4, 32), 256>>>(Tq, 256, buf2 + 128, 384, W2, lg, 1, 16);
    softmax_kernel<<<smGrid, 256>>>(lg, dmsk, b2, probs, 0, 8);
    sgemm_kernel<<<dim3(4, 8, 4), 256>>>(probs, buf2, 0, ctx, 0, 0, 0, 0,
                                         256, 256, 384, 128,
                                         (long)SEQ * SEQ, (long)SEQ * 384, (long)SEQ * 128, 0);
    gemm_ln_kernel<<<MROWS / 8, 256>>>(ctx, Wd2, bd2, o1, ln2g, ln2b, o2, 128);

    // ---- FFN ----
    sgemm_kernel<<<dim3(16, 32, 1), 256>>>(o2, Wf1, bf1, fh, 0, 0, 0, 0,
                                           128, 128, 512, 512, 0, 0, 0, 1);
    gemm_ln_kernel<<<MROWS / 8, 256>>>(fh, Wf2, bf2, o2, ln3g, ln3b, out, 512);
}

// round 5
// speedup vs baseline: 1.0710x; 1.0710x over previous
#include <cuda_runtime.h>

#define BSZ 4
#define SEQ 256
#define DIM 128
#define HID 128
#define DFF 512
#define MROWS (BSZ*SEQ)   // 1024
#define LGSZ (BSZ*SEQ*SEQ)

// ---------------- scratch (device globals; no allocations) ----------------
__device__ float g_Wbig1[DIM*384];
__device__ float g_Wbig2[DIM*384];
__device__ float g_bbig1[384];
__device__ float g_bbig2[384];
__device__ float g_buf1[MROWS*384];   // [v1 | T1A | T1B]
__device__ float g_buf2[MROWS*384];   // [pk | TkA | TkB]
__device__ float g_Tq  [MROWS*256];   // [TqA | TqB]
__device__ float g_lg  [4*LGSZ];      // sim partials (4 H-quarters)
__device__ float g_probs[LGSZ];
__device__ float g_ctx[MROWS*DIM];
__device__ float g_tmp[MROWS*DIM];
__device__ float g_o1 [MROWS*DIM];
__device__ float g_o2 [MROWS*DIM];
__device__ float g_fh [MROWS*DFF];

// ---------------- prep: biases  bbig = [bw | bw@[W1q|W1k] + [b1|0]] --------
__global__ void prep_bias_kernel(const float* __restrict__ bw1, const float* __restrict__ bw2,
                                 const float* __restrict__ W1q, const float* __restrict__ W1k,
                                 const float* __restrict__ b1,
                                 float* __restrict__ bbig1, float* __restrict__ bbig2)
{
    const float* bw = blockIdx.x ? bw2 : bw1;
    float* outp = blockIdx.x ? bbig2 : bbig1;
    int n = threadIdx.x;                 // 0..383
    if (n < 128) { outp[n] = bw[n]; return; }
    int np = n - 128;
    const float* Wsrc = (np < 128) ? W1q : W1k;
    int col = np & 127;
    float s = (np < 128) ? b1[col] : 0.f;
    for (int k = 0; k < 128; k++) s += bw[k] * Wsrc[k * 128 + col];
    outp[n] = s;
}

// ---------------- prep: Wbig = [Ww | Ww@W1q | Ww@W1k]  (128x384) -----------
__global__ void prep_wbig_kernel(const float* __restrict__ Ww1, const float* __restrict__ Ww2,
                                 const float* __restrict__ W1q, const float* __restrict__ W1k,
                                 float* __restrict__ Wbig1, float* __restrict__ Wbig2)
{
    const float* Ww = blockIdx.z ? Ww2 : Ww1;
    float* Wbig = blockIdx.z ? Wbig2 : Wbig1;
    int bx = blockIdx.x, m0 = blockIdx.y * 32;
    int tid = threadIdx.x;
    if (bx < 4) {                        // copy Ww into cols [0,128)
        int n0 = bx * 32;
        for (int idx = tid; idx < 1024; idx += 256) {
            int mm = idx >> 5, nn = idx & 31;
            Wbig[(m0 + mm) * 384 + n0 + nn] = Ww[(m0 + mm) * 128 + n0 + nn];
        }
        return;
    }
    int n0p = (bx - 4) * 32;
    const float* Bsrc = (n0p < 128) ? (W1q + n0p) : (W1k + n0p - 128);
    __shared__ float As[32][34], Bs[32][34];
    int tx = tid & 15, ty = tid >> 4;
    float a00 = 0.f, a01 = 0.f, a10 = 0.f, a11 = 0.f;
    for (int k0 = 0; k0 < 128; k0 += 32) {
        #pragma unroll
        for (int i = 0; i < 4; i++) {
            int idx = tid + i * 256;
            int ka = idx & 31, ma = idx >> 5;
            As[ka][ma] = Ww[(m0 + ma) * 128 + k0 + ka];
            int nb = idx & 31, kb = idx >> 5;
            Bs[kb][nb] = Bsrc[(k0 + kb) * 128 + nb];
        }
        __syncthreads();
        #pragma unroll
        for (int kk = 0; kk < 32; kk++) {
            float2 a = *(const float2*)&As[kk][ty * 2];
            float2 b = *(const float2*)&Bs[kk][tx * 2];
            a00 += a.x * b.x; a01 += a.x * b.y;
            a10 += a.y * b.x; a11 += a.y * b.y;
        }
        __syncthreads();
    }
    int m = m0 + ty * 2, n = 128 + n0p + tx * 2;
    Wbig[m * 384 + n]           = a00;
    Wbig[m * 384 + n + 1]       = a01;
    Wbig[(m + 1) * 384 + n]     = a10;
    Wbig[(m + 1) * 384 + n + 1] = a11;
}

// ---------------- SGEMM 32x32, 256 thr, 2x2 micro (R3-proven), general lds -
// set0 with z-strides; set1 (if C1) used when blockIdx.z==1.
__global__ void sgemm_kernel(const float* __restrict__ A0, const float* __restrict__ B0,
                             const float* __restrict__ bias0, float* __restrict__ C0,
                             const float* __restrict__ A1, const float* __restrict__ B1,
                             const float* __restrict__ bias1, float* __restrict__ C1,
                             int K, int lda, int ldb, int ldc,
                             long sA, long sB, long sC, int relu)
{
    __shared__ float As[32][34];
    __shared__ float Bs[32][34];
    int z = blockIdx.z;
    bool use1 = (z == 1) && (C1 != 0);
    const float* A = use1 ? A1 : A0 + (long)z * sA;
    const float* B = use1 ? B1 : B0 + (long)z * sB;
    const float* bias = use1 ? bias1 : bias0;
    float* C = use1 ? C1 : C0 + (long)z * sC;
    int m0 = blockIdx.y * 32, n0 = blockIdx.x * 32;
    int tid = threadIdx.x;
    int tx = tid & 15, ty = tid >> 4;
    float acc00 = 0.f, acc01 = 0.f, acc10 = 0.f, acc11 = 0.f;

    for (int k0 = 0; k0 < K; k0 += 32) {
        #pragma unroll
        for (int i = 0; i < 4; i++) {
            int idx = tid + i * 256;
            int ka = idx & 31, ma = idx >> 5;
            As[ka][ma] = A[(long)(m0 + ma) * lda + k0 + ka];
            int nb = idx & 31, kb = idx >> 5;
            Bs[kb][nb] = B[(long)(k0 + kb) * ldb + n0 + nb];
        }
        __syncthreads();
        #pragma unroll
        for (int kk = 0; kk < 32; kk++) {
            float2 a = *(const float2*)&As[kk][ty * 2];
            float2 b = *(const float2*)&Bs[kk][tx * 2];
            acc00 += a.x * b.x; acc01 += a.x * b.y;
            acc10 += a.y * b.x; acc11 += a.y * b.y;
        }
        __syncthreads();
    }
    int m = m0 + ty * 2, n = n0 + tx * 2;
    float bb0 = bias ? bias[n]     : 0.f;
    float bb1 = bias ? bias[n + 1] : 0.f;
    float v00 = acc00 + bb0, v01 = acc01 + bb1;
    float v10 = acc10 + bb0, v11 = acc11 + bb1;
    if (relu) {
        v00 = fmaxf(v00, 0.f); v01 = fmaxf(v01, 0.f);
        v10 = fmaxf(v10, 0.f); v11 = fmaxf(v11, 0.f);
    }
    C[(long)m * ldc + n]           = v00;
    C[(long)m * ldc + n + 1]       = v01;
    C[(long)(m + 1) * ldc + n]     = v10;
    C[(long)(m + 1) * ldc + n + 1] = v11;
}

// ---------------- SGEMM 32x64 tile, 256 thr, 2x4 micro ---------------------
// higher arithmetic intensity; for wide-N GEMMs with grid >= ~128 blocks.
__global__ void sgemm2x4_kernel(const float* __restrict__ A0, const float* __restrict__ B0,
                                const float* __restrict__ bias0, float* __restrict__ C0,
                                const float* __restrict__ A1, const float* __restrict__ B1,
                                const float* __restrict__ bias1, float* __restrict__ C1,
                                int K, int lda, int ldb, int ldc, int relu)
{
    __shared__ float As[32][34];
    __shared__ float Bs[32][68];
    int z = blockIdx.z;
    bool use1 = (z == 1) && (C1 != 0);
    const float* A = use1 ? A1 : A0;
    const float* B = use1 ? B1 : B0;
    const float* bias = use1 ? bias1 : bias0;
    float* C = use1 ? C1 : C0;
    int m0 = blockIdx.y * 32, n0 = blockIdx.x * 64;
    int tid = threadIdx.x;
    int tx = tid & 15, ty = tid >> 4;
    float acc[2][4] = {};

    for (int k0 = 0; k0 < K; k0 += 32) {
        #pragma unroll
        for (int i = 0; i < 4; i++) {          // A: 32m x 32k
            int idx = tid + i * 256;
            int ka = idx & 31, ma = idx >> 5;
            As[ka][ma] = A[(long)(m0 + ma) * lda + k0 + ka];
        }
        #pragma unroll
        for (int i = 0; i < 8; i++) {          // B: 32k x 64n
            int idx = tid + i * 256;           // 0..2047
            int nb = idx & 63, kb = idx >> 6;
            Bs[kb][nb] = B[(long)(k0 + kb) * ldb + n0 + nb];
        }
        __syncthreads();
        #pragma unroll
        for (int kk = 0; kk < 32; kk++) {
            float2 a = *(const float2*)&As[kk][ty * 2];
            float4 b = *(const float4*)&Bs[kk][tx * 4];
            float bv[4] = {b.x, b.y, b.z, b.w};
            #pragma unroll
            for (int j = 0; j < 4; j++) {
                acc[0][j] += a.x * bv[j];
                acc[1][j] += a.y * bv[j];
            }
        }
        __syncthreads();
    }
    int m = m0 + ty * 2, n = n0 + tx * 4;
    float bb[4] = {0.f, 0.f, 0.f, 0.f};
    if (bias) {
        #pragma unroll
        for (int j = 0; j < 4; j++) bb[j] = bias[n + j];
    }
    #pragma unroll
    for (int i = 0; i < 2; i++) {
        float4 o4;
        float v0 = acc[i][0] + bb[0], v1 = acc[i][1] + bb[1];
        float v2 = acc[i][2] + bb[2], v3 = acc[i][3] + bb[3];
        if (relu) { v0=fmaxf(v0,0.f); v1=fmaxf(v1,0.f); v2=fmaxf(v2,0.f); v3=fmaxf(v3,0.f); }
        o4.x=v0; o4.y=v1; o4.z=v2; o4.w=v3;
        *(float4*)&C[(long)(m + i) * ldc + n] = o4;
    }
}

// ---------------- pairwise similarity (R3-proven shape, strided inputs) ----
// q rows at qbase (stride ldq): A-part +0, B-part +128; same layout at kbase.
// term1 = relu(Aq + Bk).W2 ; term2 (dual) = relu(Ak + Bq).W2
// z = b*4 + hq ; H-quarter [hq*32,+32) -> partial into lg + hq*LGSZ.
__global__ void sim_kernel(const float* __restrict__ qbase, int ldq,
                           const float* __restrict__ kbase, int ldk,
                           const float* __restrict__ W2,
                           float* __restrict__ lg, int dual)
{
    __shared__ float sqa[32][34];  // term1 q-side [h][q]
    __shared__ float sqb[32][34];  // term2 q-side
    __shared__ float skb[32][68];  // term1 k-side [h][k]
    __shared__ float ska[32][68];  // term2 k-side
    __shared__ float sw[32];

    int z = blockIdx.z, b = z >> 2, hq = z & 3;
    int h0 = hq * 32;
    int q0 = blockIdx.y * 32, k0 = blockIdx.x * 64;
    const float* qp = qbase + (long)(b * SEQ + q0) * ldq;
    const float* kp = kbase + (long)(b * SEQ + k0) * ldk;
    int tid = threadIdx.x;
    int tx = tid & 15, ty = tid >> 4;
    float acc[2][4] = {};

    #pragma unroll
    for (int i = 0; i < 4; i++) {          // q-side: 32 rows x 32 h
        int idx = tid + i * 256;
        int r = idx >> 5, h = idx & 31;
        sqa[h][r] = qp[(long)r * ldq + h0 + h];
        if (dual) sqb[h][r] = qp[(long)r * ldq + 128 + h0 + h];
    }
    #pragma unroll
    for (int i = 0; i < 8; i++) {          // k-side: 64 rows x 32 h
        int idx = tid + i * 256;
        int r = idx >> 5, h = idx & 31;
        skb[h][r] = kp[(long)r * ldk + 128 + h0 + h];
        if (dual) ska[h][r] = kp[(long)r * ldk + h0 + h];
    }
    if (tid < 32) sw[tid] = W2[h0 + tid];
    __syncthreads();

    #pragma unroll 4
    for (int h = 0; h < 32; h++) {
        float w = sw[h];
        float2 a1r = *(const float2*)&sqa[h][ty * 2];
        float4 b1r = *(const float4*)&skb[h][tx * 4];
        float a1v[2] = {a1r.x, a1r.y};
        float b1v[4] = {b1r.x, b1r.y, b1r.z, b1r.w};
        #pragma unroll
        for (int i = 0; i < 2; i++)
            #pragma unroll
            for (int j = 0; j < 4; j++)
                acc[i][j] += fmaxf(a1v[i] + b1v[j], 0.f) * w;
        if (dual) {
            float2 qb = *(const float2*)&sqb[h][ty * 2];
            float4 ka = *(const float4*)&ska[h][tx * 4];
            float qv[2] = {qb.x, qb.y};
            float kv[4] = {ka.x, ka.y, ka.z, ka.w};
            #pragma unroll
            for (int i = 0; i < 2; i++)
                #pragma unroll
                for (int j = 0; j < 4; j++)
                    acc[i][j] += fmaxf(kv[j] + qv[i], 0.f) * w;
        }
    }

    float* outp = lg + (long)hq * LGSZ;
    #pragma unroll
    for (int i = 0; i < 2; i++) {
        int q = q0 + ty * 2 + i;
        #pragma unroll
        for (int j = 0; j < 4; j++) {
            int k = k0 + tx * 4 + j;
            outp[((long)b * SEQ + q) * SEQ + k] = acc[i][j];
        }
    }
}

// ---------------- masked softmax; sums 4 H-partials; sym adds transpose ----
__global__ void softmax_kernel(const float* __restrict__ lg,
                               const float* __restrict__ mask, const float* __restrict__ b2p,
                               float* __restrict__ probs, int sym)
{
    int q = blockIdx.x, b = blockIdx.y;
    long row = ((long)b * SEQ + q) * SEQ;
    int t = threadIdx.x;
    __shared__ float red[8];

    float x = 0.f;
    #pragma unroll
    for (int p = 0; p < 4; p++) x += lg[(long)p * LGSZ + row + t];
    if (sym) {
        long col = ((long)b * SEQ + t) * SEQ + q;
        #pragma unroll
        for (int p = 0; p < 4; p++) x += lg[(long)p * LGSZ + col];
    }
    x += 2.f * b2p[0] + mask[row + t] * (-1e9f);

    float m = x;
    #pragma unroll
    for (int o = 16; o; o >>= 1) m = fmaxf(m, __shfl_xor_sync(0xffffffffu, m, o));
    if ((t & 31) == 0) red[t >> 5] = m;
    __syncthreads();
    m = red[0];
    #pragma unroll
    for (int i = 1; i < 8; i++) m = fmaxf(m, red[i]);

    float e = __expf(x - m);
    float s = e;
    #pragma unroll
    for (int o = 16; o; o >>= 1) s += __shfl_xor_sync(0xffffffffu, s, o);
    __syncthreads();
    if ((t & 31) == 0) red[t >> 5] = s;
    __syncthreads();
    s = red[0] + red[1] + red[2] + red[3] + red[4] + red[5] + red[6] + red[7];
    probs[row + t] = e / s;
}

// ---------------- fused residual add + LayerNorm (warp per 128-row) --------
__global__ void add_ln_kernel(const float* __restrict__ a, const float* __restrict__ r,
                              const float* __restrict__ g, const float* __restrict__ be,
                              float* __restrict__ out)
{
    int row  = blockIdx.x * 8 + (threadIdx.x >> 5);
    int lane = threadIdx.x & 31;
    long base = (long)row * DIM + lane * 4;
    float4 av = *(const float4*)(a + base);
    float4 rv = *(const float4*)(r + base);
    float v[4] = {av.x + rv.x, av.y + rv.y, av.z + rv.z, av.w + rv.w};
    float s = v[0] + v[1] + v[2] + v[3];
    #pragma unroll
    for (int o = 16; o; o >>= 1) s += __shfl_xor_sync(0xffffffffu, s, o);
    float mean = s * (1.f / DIM);
    float vs = 0.f;
    #pragma unroll
    for (int j = 0; j < 4; j++) { float d = v[j] - mean; vs += d * d; }
    #pragma unroll
    for (int o = 16; o; o >>= 1) vs += __shfl_xor_sync(0xffffffffu, vs, o);
    float inv = rsqrtf(vs * (1.f / DIM) + 1e-6f);
    float4 gv = *(const float4*)(g + lane * 4);
    float4 bv = *(const float4*)(be + lane * 4);
    float4 o4;
    o4.x = (v[0] - mean) * inv * gv.x + bv.x;
    o4.y = (v[1] - mean) * inv * gv.y + bv.y;
    o4.z = (v[2] - mean) * inv * gv.z + bv.z;
    o4.w = (v[3] - mean) * inv * gv.w + bv.w;
    *(float4*)(out + base) = o4;
}

// ---------------- host orchestration ----------------
extern "C" void kernel_launch(void* const* d_in, const int* in_sizes, int n_in,
                              void* d_out, int out_size)
{
    (void)in_sizes; (void)n_in; (void)out_size;
    const float* x    = (const float*)d_in[0];
    const float* enc  = (const float*)d_in[1];
    const float* cmsk = (const float*)d_in[2];
    const float* dmsk = (const float*)d_in[3];
    const float* W1q  = (const float*)d_in[4];
    const float* W1k  = (const float*)d_in[5];
    const float* b1   = (const float*)d_in[6];
    const float* W2   = (const float*)d_in[7];
    const float* b2   = (const float*)d_in[8];
    const float* Ww1  = (const float*)d_in[9];
    const float* bw1  = (const float*)d_in[10];
    const float* Wd1  = (const float*)d_in[11];
    const float* bd1  = (const float*)d_in[12];
    const float* Ww2  = (const float*)d_in[13];
    const float* bw2  = (const float*)d_in[14];
    const float* Wd2  = (const float*)d_in[15];
    const float* bd2  = (const float*)d_in[16];
    const float* Wf1  = (const float*)d_in[17];
    const float* bf1  = (const float*)d_in[18];
    const float* Wf2  = (const float*)d_in[19];
    const float* bf2  = (const float*)d_in[20];
    const float* ln1g = (const float*)d_in[21];
    const float* ln1b = (const float*)d_in[22];
    const float* ln2g = (const float*)d_in[23];
    const float* ln2b = (const float*)d_in[24];
    const float* ln3g = (const float*)d_in[25];
    const float* ln3b = (const float*)d_in[26];
    float* out = (float*)d_out;

    float *Wb1, *Wb2, *bb1, *bb2, *buf1, *buf2, *Tq, *lg, *probs, *ctx, *tmp, *o1, *o2, *fh;
    cudaGetSymbolAddress((void**)&Wb1,   g_Wbig1);
    cudaGetSymbolAddress((void**)&Wb2,   g_Wbig2);
    cudaGetSymbolAddress((void**)&bb1,   g_bbig1);
    cudaGetSymbolAddress((void**)&bb2,   g_bbig2);
    cudaGetSymbolAddress((void**)&buf1,  g_buf1);
    cudaGetSymbolAddress((void**)&buf2,  g_buf2);
    cudaGetSymbolAddress((void**)&Tq,    g_Tq);
    cudaGetSymbolAddress((void**)&lg,    g_lg);
    cudaGetSymbolAddress((void**)&probs, g_probs);
    cudaGetSymbolAddress((void**)&ctx,   g_ctx);
    cudaGetSymbolAddress((void**)&tmp,   g_tmp);
    cudaGetSymbolAddress((void**)&o1,    g_o1);
    cudaGetSymbolAddress((void**)&o2,    g_o2);
    cudaGetSymbolAddress((void**)&fh,    g_fh);

    dim3 simGrid(SEQ / 64, SEQ / 32, BSZ * 4);   // (4, 8, 16) = 512 blocks
    dim3 smGrid(SEQ, BSZ);

    // ---- prep (weights only) ----
    prep_bias_kernel<<<2, 384>>>(bw1, bw2, W1q, W1k, b1, bb1, bb2);
    prep_wbig_kernel<<<dim3(12, 4, 2), 256>>>(Ww1, Ww2, W1q, W1k, Wb1, Wb2);

    // ---- batched projection: buf1 = x@Wbig1+bbig1, buf2 = enc@Wbig2+bbig2 ----
    sgemm2x4_kernel<<<dim3(6, 32, 2), 256>>>(x, Wb1, bb1, buf1,
                                             enc, Wb2, bb2, buf2,
                                             128, 128, 384, 384, 0);

    // ---- self-attention: logits = S + S^T (symmetry) ----
    sim_kernel<<<simGrid, 256>>>(buf1 + 128, 384, buf1 + 128, 384, W2, lg, 0);
    softmax_kernel<<<smGrid, 256>>>(lg, cmsk, b2, probs, 1);
    sgemm_kernel<<<dim3(4, 8, 4), 256>>>(probs, buf1, 0, ctx, 0, 0, 0, 0,
                                         256, 256, 384, 128,
                                         (long)SEQ * SEQ, (long)SEQ * 384, (long)SEQ * 128, 0);
    sgemm_kernel<<<dim3(4, 32, 1), 256>>>(ctx, Wd1, bd1, tmp, 0, 0, 0, 0,
                                          128, 128, 128, 128, 0, 0, 0, 0);
    add_ln_kernel<<<MROWS / 8, 256>>>(tmp, x, ln1g, ln1b, o1);

    // ---- cross-attention: Tq = o1 @ Wbig2[:,128:384] + bbig2[128:] ----
    sgemm2x4_kernel<<<dim3(4, 32, 1), 256>>>(o1, Wb2 + 128, bb2 + 128, Tq,
                                             0, 0, 0, 0,
                                             128, 128, 384, 256, 0);
    sim_kernel<<<simGrid, 256>>>(Tq, 256, buf2 + 128, 384, W2, lg, 1);
    softmax_kernel<<<smGrid, 256>>>(lg, dmsk, b2, probs, 0);
    sgemm_kernel<<<dim3(4, 8, 4), 256>>>(probs, buf2, 0, ctx, 0, 0, 0, 0,
                                         256, 256, 384, 128,
                                         (long)SEQ * SEQ, (long)SEQ * 384, (long)SEQ * 128, 0);
    sgemm_kernel<<<dim3(4, 32, 1), 256>>>(ctx, Wd2, bd2, tmp, 0, 0, 0, 0,
                                          128, 128, 128, 128, 0, 0, 0, 0);
    add_ln_kernel<<<MROWS / 8, 256>>>(tmp, o1, ln2g, ln2b, o2);

    // ---- FFN ----
    sgemm2x4_kernel<<<dim3(8, 32, 1), 256>>>(o2, Wf1, bf1, fh, 0, 0, 0, 0,
                                             128, 128, 512, 512, 1);
    sgemm_kernel<<<dim3(4, 32, 1), 256>>>(fh, Wf2, bf2, tmp, 0, 0, 0, 0,
                                          512, 512, 128, 128, 0, 0, 0, 0);
    add_ln_kernel<<<MROWS / 8, 256>>>(tmp, o2, ln3g, ln3b, out);
}